// round 3
// baseline (speedup 1.0000x reference)
#include <cuda_runtime.h>

// Problem constants
#define BATCH 2
#define SEQ   2048
#define DMODEL 768
#define NHEAD 12
#define HDIM  64
#define MROWS (BATCH*SEQ)   // 4096

// Scratch for Q/K/V in [B, H, S, hd] layout (12 MB each) — device globals, no allocs.
__device__ float g_q[BATCH*NHEAD*SEQ*HDIM];
__device__ float g_k[BATCH*NHEAD*SEQ*HDIM];
__device__ float g_v[BATCH*NHEAD*SEQ*HDIM];

// ---------------------------------------------------------------------------
// Kernel 1: fused QKV projection.  out = X @ W + b, written to [B,H,S,hd].
// Tiled SGEMM: 64x64 tile, BK=16, 256 threads, 4x4 microtile per thread.
// blockIdx.z in {0,1,2} selects Q/K/V.
// ---------------------------------------------------------------------------
__global__ __launch_bounds__(256) void qkv_kernel(
    const float* __restrict__ X,
    const float* __restrict__ Wq, const float* __restrict__ bq,
    const float* __restrict__ Wk, const float* __restrict__ bk,
    const float* __restrict__ Wv, const float* __restrict__ bv)
{
    const int z = blockIdx.z;
    const float* __restrict__ W    = (z == 0) ? Wq : (z == 1) ? Wk : Wv;
    const float* __restrict__ bias = (z == 0) ? bq : (z == 1) ? bk : bv;
    float* __restrict__ out        = (z == 0) ? g_q : (z == 1) ? g_k : g_v;

    __shared__ float As[16][65];   // [k][m], padded
    __shared__ float Bs[16][64];   // [k][n]

    const int tid = threadIdx.x;
    const int tx = tid & 15;
    const int ty = tid >> 4;
    const int m0 = blockIdx.y * 64;
    const int n0 = blockIdx.x * 64;

    float acc[4][4] = {};

    for (int k0 = 0; k0 < DMODEL; k0 += 16) {
        // Load A tile: 64 rows x 16 cols  (1024 elems / 256 threads)
        #pragma unroll
        for (int e = 0; e < 4; e++) {
            int idx = tid + e * 256;
            int r = idx >> 4, c = idx & 15;
            As[c][r] = X[(m0 + r) * DMODEL + k0 + c];
        }
        // Load B tile: 16 rows x 64 cols
        #pragma unroll
        for (int e = 0; e < 4; e++) {
            int idx = tid + e * 256;
            int r = idx >> 6, c = idx & 63;
            Bs[r][c] = W[(k0 + r) * DMODEL + n0 + c];
        }
        __syncthreads();

        #pragma unroll
        for (int k = 0; k < 16; k++) {
            float a[4], b[4];
            #pragma unroll
            for (int i = 0; i < 4; i++) a[i] = As[k][ty + 16 * i];
            #pragma unroll
            for (int j = 0; j < 4; j++) b[j] = Bs[k][tx + 16 * j];
            #pragma unroll
            for (int i = 0; i < 4; i++)
                #pragma unroll
                for (int j = 0; j < 4; j++)
                    acc[i][j] += a[i] * b[j];
        }
        __syncthreads();
    }

    // Epilogue: add bias, scatter into [B,H,S,hd]
    #pragma unroll
    for (int i = 0; i < 4; i++) {
        int mg = m0 + ty + 16 * i;          // global row in [0,4096)
        int bb = mg >> 11;                  // / SEQ
        int s  = mg & (SEQ - 1);
        #pragma unroll
        for (int j = 0; j < 4; j++) {
            int ng = n0 + tx + 16 * j;      // global col in [0,768)
            int h  = ng >> 6;
            int d  = ng & 63;
            out[((bb * NHEAD + h) * SEQ + s) * HDIM + d] = acc[i][j] + bias[ng];
        }
    }
}

// ---------------------------------------------------------------------------
// Kernel 2: flash attention.  One block per (b,h, q-tile of 64 rows).
// BM=BN=64, online softmax, O[64][64] in registers (4x4 per thread).
// smem: Qs/Ks/Vs each [64][65] fp32 (padded, conflict-free).  Ks reused as Ps.
// ---------------------------------------------------------------------------
__global__ __launch_bounds__(256) void attn_kernel(
    const float* __restrict__ mask, float* __restrict__ out)
{
    extern __shared__ float smem[];
    float* Qs = smem;              // [64][65]
    float* Ks = smem + 64 * 65;    // [64][65], reused as P
    float* Vs = Ks  + 64 * 65;     // [64][65]

    const int pair = blockIdx.y;
    const int bb = pair / NHEAD;
    const int h  = pair % NHEAD;
    const int q0 = blockIdx.x * 64;

    const int tid = threadIdx.x;
    const int tx = tid & 15;
    const int ty = tid >> 4;

    const float* __restrict__ Qg = g_q + (bb * NHEAD + h) * SEQ * HDIM;
    const float* __restrict__ Kg = g_k + (bb * NHEAD + h) * SEQ * HDIM;
    const float* __restrict__ Vg = g_v + (bb * NHEAD + h) * SEQ * HDIM;

    // Load Q tile once (4096 elems / 256 threads = 16 each)
    #pragma unroll
    for (int e = 0; e < 16; e++) {
        int idx = tid + e * 256;
        int r = idx >> 6, d = idx & 63;
        Qs[r * 65 + d] = Qg[(q0 + r) * HDIM + d];
    }

    float m_r[4], l_r[4], o[4][4] = {};
    #pragma unroll
    for (int i = 0; i < 4; i++) { m_r[i] = -1e30f; l_r[i] = 0.f; }

    for (int k0 = 0; k0 < SEQ; k0 += 64) {
        __syncthreads();  // previous-iter reads of Ks/Vs done; also covers Q load on iter 0
        #pragma unroll
        for (int e = 0; e < 16; e++) {
            int idx = tid + e * 256;
            int r = idx >> 6, d = idx & 63;
            Ks[r * 65 + d] = Kg[(k0 + r) * HDIM + d];
            Vs[r * 65 + d] = Vg[(k0 + r) * HDIM + d];
        }
        __syncthreads();

        // S = Q K^T  (64x64 tile, 4x4 per thread)
        float s[4][4] = {};
        #pragma unroll
        for (int d = 0; d < 64; d++) {
            float a[4], b[4];
            #pragma unroll
            for (int i = 0; i < 4; i++) a[i] = Qs[(ty + 16 * i) * 65 + d];
            #pragma unroll
            for (int j = 0; j < 4; j++) b[j] = Ks[(tx + 16 * j) * 65 + d];
            #pragma unroll
            for (int i = 0; i < 4; i++)
                #pragma unroll
                for (int j = 0; j < 4; j++)
                    s[i][j] += a[i] * b[j];
        }

        // scale + additive mask (mask indexed by key position)
        float mk[4];
        #pragma unroll
        for (int j = 0; j < 4; j++)
            mk[j] = mask[bb * SEQ + k0 + tx + 16 * j];

        // online softmax update.  Row r = ty+16*i is owned by the 16 lanes
        // sharing ty (contiguous half-warp) -> shfl width-16 reductions.
        #pragma unroll
        for (int i = 0; i < 4; i++) {
            float mm = -1e30f;
            #pragma unroll
            for (int j = 0; j < 4; j++) {
                s[i][j] = s[i][j] * 0.125f + mk[j];   // 1/sqrt(64)
                mm = fmaxf(mm, s[i][j]);
            }
            #pragma unroll
            for (int off = 8; off > 0; off >>= 1)
                mm = fmaxf(mm, __shfl_xor_sync(0xffffffffu, mm, off, 16));

            float mn = fmaxf(m_r[i], mm);
            float alpha = __expf(m_r[i] - mn);
            m_r[i] = mn;

            float ps = 0.f;
            #pragma unroll
            for (int j = 0; j < 4; j++) {
                s[i][j] = __expf(s[i][j] - mn);
                ps += s[i][j];
            }
            #pragma unroll
            for (int off = 8; off > 0; off >>= 1)
                ps += __shfl_xor_sync(0xffffffffu, ps, off, 16);

            l_r[i] = l_r[i] * alpha + ps;
            #pragma unroll
            for (int j = 0; j < 4; j++) o[i][j] *= alpha;
        }

        __syncthreads();   // all threads done reading Ks as K
        // stage P into Ks region
        #pragma unroll
        for (int i = 0; i < 4; i++)
            #pragma unroll
            for (int j = 0; j < 4; j++)
                Ks[(ty + 16 * i) * 65 + tx + 16 * j] = s[i][j];
        __syncthreads();

        // O += P @ V
        #pragma unroll
        for (int c = 0; c < 64; c++) {
            float a[4], b[4];
            #pragma unroll
            for (int i = 0; i < 4; i++) a[i] = Ks[(ty + 16 * i) * 65 + c];
            #pragma unroll
            for (int j = 0; j < 4; j++) b[j] = Vs[c * 65 + tx + 16 * j];
            #pragma unroll
            for (int i = 0; i < 4; i++)
                #pragma unroll
                for (int j = 0; j < 4; j++)
                    o[i][j] += a[i] * b[j];
        }
    }

    // Normalize and write out in [B,S,D]
    #pragma unroll
    for (int i = 0; i < 4; i++) {
        int r = q0 + ty + 16 * i;
        float inv = 1.f / l_r[i];
        #pragma unroll
        for (int j = 0; j < 4; j++) {
            int d = tx + 16 * j;
            out[(bb * SEQ + r) * DMODEL + h * HDIM + d] = o[i][j] * inv;
        }
    }
}

// ---------------------------------------------------------------------------
extern "C" void kernel_launch(void* const* d_in, const int* in_sizes, int n_in,
                              void* d_out, int out_size)
{
    const float* v1   = (const float*)d_in[0];
    const float* mask = (const float*)d_in[1];
    const float* Wq   = (const float*)d_in[2];
    const float* bq   = (const float*)d_in[3];
    const float* Wk   = (const float*)d_in[4];
    const float* bk   = (const float*)d_in[5];
    const float* Wv   = (const float*)d_in[6];
    const float* bv   = (const float*)d_in[7];
    float* out = (float*)d_out;

    // QKV projections: grid (N-tiles, M-tiles, 3)
    dim3 g1(DMODEL / 64, MROWS / 64, 3);
    qkv_kernel<<<g1, 256>>>(v1, Wq, bq, Wk, bk, Wv, bv);

    // Attention: grid (q-tiles, B*H).  49920 B dynamic smem (> 48 KB static cap).
    const int smem_bytes = 3 * 64 * 65 * (int)sizeof(float);
    cudaFuncSetAttribute(attn_kernel, cudaFuncAttributeMaxDynamicSharedMemorySize,
                         smem_bytes);
    dim3 g2(SEQ / 64, BATCH * NHEAD);
    attn_kernel<<<g2, 256, smem_bytes>>>(mask, out);
}

// round 6
// speedup vs baseline: 3.6150x; 3.6150x over previous
#include <cuda_runtime.h>
#include <cstdint>

#define BATCH 2
#define SEQ   2048
#define DMODEL 768
#define NHEAD 12
#define HDIM  64
#define MROWS (BATCH*SEQ)   // 4096

// Scratch Q/K/V in [B,H,S,hd] fp32 (device globals, no allocs)
__device__ float g_q[BATCH*NHEAD*SEQ*HDIM];
__device__ float g_k[BATCH*NHEAD*SEQ*HDIM];
__device__ float g_v[BATCH*NHEAD*SEQ*HDIM];

// ---------------------------------------------------------------------------
// tf32 helpers
// ---------------------------------------------------------------------------
__device__ __forceinline__ uint32_t f2tf(float x) {
    uint32_t u;
    asm("cvt.rna.tf32.f32 %0, %1;" : "=r"(u) : "f"(x));
    return u;
}
__device__ __forceinline__ void split_tf(float x, uint32_t& h, uint32_t& l) {
    h = f2tf(x);
    l = f2tf(x - __uint_as_float(h));
}
// D += A(m16k8,row) * B(k8n8,col), tf32 inputs, fp32 accum
__device__ __forceinline__ void mma8(float* c,
    uint32_t a0, uint32_t a1, uint32_t a2, uint32_t a3,
    uint32_t b0, uint32_t b1)
{
    asm volatile(
        "mma.sync.aligned.m16n8k8.row.col.f32.tf32.tf32.f32 "
        "{%0,%1,%2,%3}, {%4,%5,%6,%7}, {%8,%9}, {%0,%1,%2,%3};"
        : "+f"(c[0]), "+f"(c[1]), "+f"(c[2]), "+f"(c[3])
        : "r"(a0), "r"(a1), "r"(a2), "r"(a3), "r"(b0), "r"(b1));
}

// ---------------------------------------------------------------------------
// Kernel 1: QKV projection, 3xTF32 (full fp32 accuracy).
// Block 128 thr (4 warps, 2x2), BM=64, BN=64, BK=16, warp tile m32xn32.
// blockIdx.z selects Q/K/V. Output scattered to [B,H,S,hd].
// ---------------------------------------------------------------------------
__global__ __launch_bounds__(128) void qkv_kernel(
    const float* __restrict__ X,
    const float* __restrict__ Wq, const float* __restrict__ bq,
    const float* __restrict__ Wk, const float* __restrict__ bk,
    const float* __restrict__ Wv, const float* __restrict__ bv)
{
    const int z = blockIdx.z;
    const float* __restrict__ W    = (z == 0) ? Wq : (z == 1) ? Wk : Wv;
    const float* __restrict__ bias = (z == 0) ? bq : (z == 1) ? bk : bv;
    float* __restrict__ out        = (z == 0) ? g_q : (z == 1) ? g_k : g_v;

    // stride 68: fragment loads (4g+t) are bank-conflict-free
    __shared__ uint32_t Ah[16][68], Al[16][68];   // X tile hi/lo, [k][m]
    __shared__ uint32_t Bh[16][68], Bl[16][68];   // W tile hi/lo, [k][n]

    const int tid  = threadIdx.x;
    const int warp = tid >> 5;
    const int lane = tid & 31;
    const int g = lane >> 2;          // group (row within frag)
    const int t = lane & 3;           // thread-in-quad (col within frag)
    const int wy = warp >> 1;         // warp m index (0..1)
    const int wx = warp & 1;          // warp n index (0..1)

    const int m0 = blockIdx.y * 64;
    const int n0 = blockIdx.x * 64;

    float acc[2][4][4] = {};

    for (int k0 = 0; k0 < DMODEL; k0 += 16) {
        __syncthreads();
        // A tile: 64 rows x 16 cols -> Ah/Al[k][m]
        #pragma unroll
        for (int e = 0; e < 8; e++) {
            int idx = tid + e * 128;
            int r = idx >> 4, c = idx & 15;
            float v = X[(m0 + r) * DMODEL + k0 + c];
            uint32_t h, l; split_tf(v, h, l);
            Ah[c][r] = h; Al[c][r] = l;
        }
        // B tile: 16 rows x 64 cols -> Bh/Bl[k][n]
        #pragma unroll
        for (int e = 0; e < 8; e++) {
            int idx = tid + e * 128;
            int r = idx >> 6, c = idx & 63;
            float v = W[(k0 + r) * DMODEL + n0 + c];
            uint32_t h, l; split_tf(v, h, l);
            Bh[r][c] = h; Bl[r][c] = l;
        }
        __syncthreads();

        #pragma unroll
        for (int kk = 0; kk < 16; kk += 8) {
            uint32_t ah[2][4], al[2][4];
            #pragma unroll
            for (int mt = 0; mt < 2; mt++) {
                int rb = wy * 32 + mt * 16;
                ah[mt][0] = Ah[kk + t][rb + g];
                ah[mt][1] = Ah[kk + t][rb + g + 8];
                ah[mt][2] = Ah[kk + t + 4][rb + g];
                ah[mt][3] = Ah[kk + t + 4][rb + g + 8];
                al[mt][0] = Al[kk + t][rb + g];
                al[mt][1] = Al[kk + t][rb + g + 8];
                al[mt][2] = Al[kk + t + 4][rb + g];
                al[mt][3] = Al[kk + t + 4][rb + g + 8];
            }
            #pragma unroll
            for (int nt = 0; nt < 4; nt++) {
                int nb = wx * 32 + nt * 8;
                uint32_t bh0 = Bh[kk + t][nb + g];
                uint32_t bh1 = Bh[kk + t + 4][nb + g];
                uint32_t bl0 = Bl[kk + t][nb + g];
                uint32_t bl1 = Bl[kk + t + 4][nb + g];
                #pragma unroll
                for (int mt = 0; mt < 2; mt++) {
                    mma8(acc[mt][nt], ah[mt][0], ah[mt][1], ah[mt][2], ah[mt][3], bh0, bh1);
                    mma8(acc[mt][nt], ah[mt][0], ah[mt][1], ah[mt][2], ah[mt][3], bl0, bl1);
                    mma8(acc[mt][nt], al[mt][0], al[mt][1], al[mt][2], al[mt][3], bh0, bh1);
                }
            }
        }
    }

    // Epilogue: +bias, scatter to [B,H,S,hd]. cols 2t,2t+1 adjacent -> float2.
    const int h = n0 >> 6;   // block spans exactly one head
    #pragma unroll
    for (int mt = 0; mt < 2; mt++) {
        #pragma unroll
        for (int hs = 0; hs < 2; hs++) {
            int mg = m0 + wy * 32 + mt * 16 + g + hs * 8;
            int bb = mg >> 11;
            int s  = mg & (SEQ - 1);
            float* orow = out + ((bb * NHEAD + h) * SEQ + s) * HDIM;
            #pragma unroll
            for (int nt = 0; nt < 4; nt++) {
                int d = wx * 32 + nt * 8 + 2 * t;
                float2 v;
                v.x = acc[mt][nt][hs * 2 + 0] + bias[n0 + d];
                v.y = acc[mt][nt][hs * 2 + 1] + bias[n0 + d + 1];
                *reinterpret_cast<float2*>(orow + d) = v;
            }
        }
    }
}

// ---------------------------------------------------------------------------
// Kernel 2: flash attention on tensor cores (single tf32).
// Block 128 thr (4 warps), BM=128 q rows, key tile 64, hd=64.
// Warp w owns q rows [w*32, w*32+32): softmax fully warp-local.
// ---------------------------------------------------------------------------
__global__ __launch_bounds__(128) void attn_kernel(
    const float* __restrict__ mask, float* __restrict__ out)
{
    extern __shared__ uint32_t sm4[];
    uint32_t* Qs = sm4;                 // [128][68] tf32
    uint32_t* Ks = Qs + 128 * 68;       // [64][68]  tf32  (key-major)
    uint32_t* Vs = Ks + 64 * 68;        // [64][72]  tf32  (key-major)
    uint32_t* Ps = Vs + 64 * 72;        // [128][68] tf32 probs
    float*    Ms = (float*)(Ps + 128 * 68);  // [64] mask tile

    const int pair = blockIdx.y;
    const int bb = pair / NHEAD;
    const int hh = pair % NHEAD;
    const int q0 = blockIdx.x * 128;

    const int tid  = threadIdx.x;
    const int warp = tid >> 5;
    const int lane = tid & 31;
    const int g = lane >> 2;
    const int t = lane & 3;
    const int wbase = warp * 32;

    const float* __restrict__ Qg = g_q + (bb * NHEAD + hh) * SEQ * HDIM;
    const float* __restrict__ Kg = g_k + (bb * NHEAD + hh) * SEQ * HDIM;
    const float* __restrict__ Vg = g_v + (bb * NHEAD + hh) * SEQ * HDIM;

    // Load Q tile (128x64) once, converting to tf32. float4 loads.
    {
        const float4* Q4 = reinterpret_cast<const float4*>(Qg + q0 * HDIM);
        #pragma unroll
        for (int e = 0; e < 16; e++) {
            int idx = tid + e * 128;           // 2048 float4s
            int r = idx >> 4, c4 = idx & 15;
            float4 v = Q4[idx];
            uint32_t* dst = Qs + r * 68 + c4 * 4;
            dst[0] = f2tf(v.x); dst[1] = f2tf(v.y);
            dst[2] = f2tf(v.z); dst[3] = f2tf(v.w);
        }
    }

    float o[2][8][4] = {};
    float m_run[2][2], l_run[2][2];
    #pragma unroll
    for (int i = 0; i < 2; i++)
        #pragma unroll
        for (int j = 0; j < 2; j++) { m_run[i][j] = -1e30f; l_run[i][j] = 0.f; }

    for (int k0 = 0; k0 < SEQ; k0 += 64) {
        __syncthreads();   // prior iter done with Ks/Vs (and Q load on iter 0)
        // Load K, V tiles (64x64 each) + mask
        {
            const float4* K4 = reinterpret_cast<const float4*>(Kg + k0 * HDIM);
            const float4* V4 = reinterpret_cast<const float4*>(Vg + k0 * HDIM);
            #pragma unroll
            for (int e = 0; e < 8; e++) {
                int idx = tid + e * 128;       // 1024 float4s
                int r = idx >> 4, c4 = idx & 15;
                float4 kv = K4[idx];
                uint32_t* dk = Ks + r * 68 + c4 * 4;
                dk[0] = f2tf(kv.x); dk[1] = f2tf(kv.y);
                dk[2] = f2tf(kv.z); dk[3] = f2tf(kv.w);
                float4 vv = V4[idx];
                uint32_t* dv = Vs + r * 72 + c4 * 4;
                dv[0] = f2tf(vv.x); dv[1] = f2tf(vv.y);
                dv[2] = f2tf(vv.z); dv[3] = f2tf(vv.w);
            }
            if (tid < 64) Ms[tid] = mask[bb * SEQ + k0 + tid];
        }
        __syncthreads();

        // ---- S = Q K^T : warp m32 x n64, k=64 ----
        float s[2][8][4] = {};
        #pragma unroll
        for (int kk = 0; kk < 8; kk++) {
            uint32_t a[2][4];
            #pragma unroll
            for (int mt = 0; mt < 2; mt++) {
                int rb = wbase + mt * 16;
                const uint32_t* q0p = Qs + (rb + g) * 68 + kk * 8;
                const uint32_t* q1p = Qs + (rb + g + 8) * 68 + kk * 8;
                a[mt][0] = q0p[t];     a[mt][1] = q1p[t];
                a[mt][2] = q0p[t + 4]; a[mt][3] = q1p[t + 4];
            }
            #pragma unroll
            for (int nt = 0; nt < 8; nt++) {
                uint32_t b0 = Ks[(nt * 8 + g) * 68 + kk * 8 + t];
                uint32_t b1 = Ks[(nt * 8 + g) * 68 + kk * 8 + t + 4];
                #pragma unroll
                for (int mt = 0; mt < 2; mt++)
                    mma8(s[mt][nt], a[mt][0], a[mt][1], a[mt][2], a[mt][3], b0, b1);
            }
        }

        // ---- online softmax (warp-local rows) ----
        #pragma unroll
        for (int mt = 0; mt < 2; mt++) {
            #pragma unroll
            for (int hs = 0; hs < 2; hs++) {
                float mm = -1e30f;
                #pragma unroll
                for (int nt = 0; nt < 8; nt++) {
                    #pragma unroll
                    for (int j = 0; j < 2; j++) {
                        float v = s[mt][nt][hs * 2 + j] * 0.125f
                                + Ms[nt * 8 + 2 * t + j];
                        s[mt][nt][hs * 2 + j] = v;
                        mm = fmaxf(mm, v);
                    }
                }
                mm = fmaxf(mm, __shfl_xor_sync(0xffffffffu, mm, 1));
                mm = fmaxf(mm, __shfl_xor_sync(0xffffffffu, mm, 2));

                float mn = fmaxf(m_run[mt][hs], mm);
                float alpha = __expf(m_run[mt][hs] - mn);
                m_run[mt][hs] = mn;

                float ps = 0.f;
                #pragma unroll
                for (int nt = 0; nt < 8; nt++) {
                    #pragma unroll
                    for (int j = 0; j < 2; j++) {
                        float p = __expf(s[mt][nt][hs * 2 + j] - mn);
                        s[mt][nt][hs * 2 + j] = p;
                        ps += p;
                    }
                }
                ps += __shfl_xor_sync(0xffffffffu, ps, 1);
                ps += __shfl_xor_sync(0xffffffffu, ps, 2);
                l_run[mt][hs] = l_run[mt][hs] * alpha + ps;

                #pragma unroll
                for (int nt = 0; nt < 8; nt++) {
                    o[mt][nt][hs * 2 + 0] *= alpha;
                    o[mt][nt][hs * 2 + 1] *= alpha;
                }
            }
        }

        // ---- stage P (tf32) into Ps: own warp's rows only ----
        #pragma unroll
        for (int mt = 0; mt < 2; mt++) {
            int rb = wbase + mt * 16;
            #pragma unroll
            for (int nt = 0; nt < 8; nt++) {
                uint2 p0, p1;
                p0.x = f2tf(s[mt][nt][0]); p0.y = f2tf(s[mt][nt][1]);
                p1.x = f2tf(s[mt][nt][2]); p1.y = f2tf(s[mt][nt][3]);
                *reinterpret_cast<uint2*>(Ps + (rb + g) * 68 + nt * 8 + 2 * t) = p0;
                *reinterpret_cast<uint2*>(Ps + (rb + g + 8) * 68 + nt * 8 + 2 * t) = p1;
            }
        }
        __syncwarp();

        // ---- O += P V : warp m32 x n64, k=64 (keys) ----
        #pragma unroll
        for (int kk = 0; kk < 8; kk++) {
            uint32_t a[2][4];
            #pragma unroll
            for (int mt = 0; mt < 2; mt++) {
                int rb = wbase + mt * 16;
                const uint32_t* p0p = Ps + (rb + g) * 68 + kk * 8;
                const uint32_t* p1p = Ps + (rb + g + 8) * 68 + kk * 8;
                a[mt][0] = p0p[t];     a[mt][1] = p1p[t];
                a[mt][2] = p0p[t + 4]; a[mt][3] = p1p[t + 4];
            }
            #pragma unroll
            for (int nt = 0; nt < 8; nt++) {
                uint32_t b0 = Vs[(kk * 8 + t) * 72 + nt * 8 + g];
                uint32_t b1 = Vs[(kk * 8 + t + 4) * 72 + nt * 8 + g];
                #pragma unroll
                for (int mt = 0; mt < 2; mt++)
                    mma8(o[mt][nt], a[mt][0], a[mt][1], a[mt][2], a[mt][3], b0, b1);
            }
        }
    }

    // ---- normalize + write out [B,S,D] ----
    #pragma unroll
    for (int mt = 0; mt < 2; mt++) {
        #pragma unroll
        for (int hs = 0; hs < 2; hs++) {
            int r = q0 + wbase + mt * 16 + g + hs * 8;
            float inv = 1.f / l_run[mt][hs];
            float* orow = out + (bb * SEQ + r) * DMODEL + hh * HDIM;
            #pragma unroll
            for (int nt = 0; nt < 8; nt++) {
                float2 v;
                v.x = o[mt][nt][hs * 2 + 0] * inv;
                v.y = o[mt][nt][hs * 2 + 1] * inv;
                *reinterpret_cast<float2*>(orow + nt * 8 + 2 * t) = v;
            }
        }
    }
}

// ---------------------------------------------------------------------------
extern "C" void kernel_launch(void* const* d_in, const int* in_sizes, int n_in,
                              void* d_out, int out_size)
{
    const float* v1   = (const float*)d_in[0];
    const float* mask = (const float*)d_in[1];
    const float* Wq   = (const float*)d_in[2];
    const float* bq   = (const float*)d_in[3];
    const float* Wk   = (const float*)d_in[4];
    const float* bk   = (const float*)d_in[5];
    const float* Wv   = (const float*)d_in[6];
    const float* bv   = (const float*)d_in[7];
    float* out = (float*)d_out;

    // QKV: grid (12 n-tiles, 64 m-tiles, 3 matrices), 128 threads
    dim3 g1(DMODEL / 64, MROWS / 64, 3);
    qkv_kernel<<<g1, 128>>>(v1, Wq, bq, Wk, bk, Wv, bv);

    // Attention: grid (16 q-tiles, 24 (b,h) pairs), 128 threads, 105.7 KB smem
    const int smem_bytes = (128 * 68 + 64 * 68 + 64 * 72 + 128 * 68 + 64) * 4;
    cudaFuncSetAttribute(attn_kernel, cudaFuncAttributeMaxDynamicSharedMemorySize,
                         smem_bytes);
    dim3 g2(SEQ / 128, BATCH * NHEAD);
    attn_kernel<<<g2, 128, smem_bytes>>>(mask, out);
}

// round 7
// speedup vs baseline: 4.0320x; 1.1153x over previous
#include <cuda_runtime.h>
#include <cstdint>

#define BATCH 2
#define SEQ   2048
#define DMODEL 768
#define NHEAD 12
#define HDIM  64
#define MROWS (BATCH*SEQ)      // 4096
#define QTILES (SEQ/128)       // 16
#define NTILES (QTILES*BATCH*NHEAD)  // 384
#define ATTN_GRID 296          // 2 CTAs x 148 SMs

// Scratch Q/K/V in [B,H,S,hd] fp32 (device globals, no allocs)
__device__ float g_q[BATCH*NHEAD*SEQ*HDIM];
__device__ float g_k[BATCH*NHEAD*SEQ*HDIM];
__device__ float g_v[BATCH*NHEAD*SEQ*HDIM];
__device__ unsigned int g_ctr;   // dynamic tile counter for attn

// ---------------------------------------------------------------------------
// tf32 helpers
// ---------------------------------------------------------------------------
__device__ __forceinline__ uint32_t f2tf(float x) {
    uint32_t u;
    asm("cvt.rna.tf32.f32 %0, %1;" : "=r"(u) : "f"(x));
    return u;
}
__device__ __forceinline__ void split_tf(float x, uint32_t& h, uint32_t& l) {
    h = f2tf(x);
    l = f2tf(x - __uint_as_float(h));
}
__device__ __forceinline__ void mma8(float* c,
    uint32_t a0, uint32_t a1, uint32_t a2, uint32_t a3,
    uint32_t b0, uint32_t b1)
{
    asm volatile(
        "mma.sync.aligned.m16n8k8.row.col.f32.tf32.tf32.f32 "
        "{%0,%1,%2,%3}, {%4,%5,%6,%7}, {%8,%9}, {%0,%1,%2,%3};"
        : "+f"(c[0]), "+f"(c[1]), "+f"(c[2]), "+f"(c[3])
        : "r"(a0), "r"(a1), "r"(a2), "r"(a3), "r"(b0), "r"(b1));
}

// ---------------------------------------------------------------------------
// Kernel 1: QKV projection, 3xTF32, register-prefetch pipelined.
// 256 thr (8 warps: wy=warp>>1 in 0..3, wx=warp&1), BM=128, BN=64, BK=16,
// warp tile m32xn32. blockIdx.z selects Q/K/V. Output scattered to [B,H,S,hd].
// ---------------------------------------------------------------------------
__global__ __launch_bounds__(256, 2) void qkv_kernel(
    const float* __restrict__ X,
    const float* __restrict__ Wq, const float* __restrict__ bq,
    const float* __restrict__ Wk, const float* __restrict__ bk,
    const float* __restrict__ Wv, const float* __restrict__ bv)
{
    // reset the attention tile counter once per launch (qkv precedes attn)
    if (blockIdx.x == 0 && blockIdx.y == 0 && blockIdx.z == 0 && threadIdx.x == 0)
        g_ctr = ATTN_GRID;

    const int z = blockIdx.z;
    const float* __restrict__ W    = (z == 0) ? Wq : (z == 1) ? Wk : Wv;
    const float* __restrict__ bias = (z == 0) ? bq : (z == 1) ? bk : bv;
    float* __restrict__ out        = (z == 0) ? g_q : (z == 1) ? g_k : g_v;

    // stride 132 (mod 32 = 4): frag loads (4t+g) conflict-free
    __shared__ uint32_t Ah[16][132], Al[16][132];   // X tile hi/lo, [k][m]
    __shared__ uint32_t Bh[16][68],  Bl[16][68];    // W tile hi/lo, [k][n]

    const int tid  = threadIdx.x;
    const int warp = tid >> 5;
    const int lane = tid & 31;
    const int g = lane >> 2;
    const int t = lane & 3;
    const int wy = warp >> 1;         // 0..3
    const int wx = warp & 1;          // 0..1

    const int m0 = blockIdx.y * 128;
    const int n0 = blockIdx.x * 64;

    float acc[2][4][4] = {};
    float pa[8], pb[4];

    // prefetch first tile
    #pragma unroll
    for (int e = 0; e < 8; e++) {
        int idx = tid + e * 256;
        pa[e] = X[(m0 + (idx >> 4)) * DMODEL + (idx & 15)];
    }
    #pragma unroll
    for (int e = 0; e < 4; e++) {
        int idx = tid + e * 256;
        pb[e] = W[(idx >> 6) * DMODEL + n0 + (idx & 63)];
    }

    for (int k0 = 0; k0 < DMODEL; k0 += 16) {
        __syncthreads();   // previous MMA loop done reading smem
        #pragma unroll
        for (int e = 0; e < 8; e++) {
            int idx = tid + e * 256;
            int r = idx >> 4, c = idx & 15;
            uint32_t h, l; split_tf(pa[e], h, l);
            Ah[c][r] = h; Al[c][r] = l;
        }
        #pragma unroll
        for (int e = 0; e < 4; e++) {
            int idx = tid + e * 256;
            int r = idx >> 6, c = idx & 63;
            uint32_t h, l; split_tf(pb[e], h, l);
            Bh[r][c] = h; Bl[r][c] = l;
        }
        __syncthreads();

        // prefetch next tile (overlaps the MMA loop below)
        if (k0 + 16 < DMODEL) {
            #pragma unroll
            for (int e = 0; e < 8; e++) {
                int idx = tid + e * 256;
                pa[e] = X[(m0 + (idx >> 4)) * DMODEL + k0 + 16 + (idx & 15)];
            }
            #pragma unroll
            for (int e = 0; e < 4; e++) {
                int idx = tid + e * 256;
                pb[e] = W[(k0 + 16 + (idx >> 6)) * DMODEL + n0 + (idx & 63)];
            }
        }

        #pragma unroll
        for (int kk = 0; kk < 16; kk += 8) {
            uint32_t ah[2][4], al[2][4];
            #pragma unroll
            for (int mt = 0; mt < 2; mt++) {
                int rb = wy * 32 + mt * 16;
                ah[mt][0] = Ah[kk + t][rb + g];
                ah[mt][1] = Ah[kk + t][rb + g + 8];
                ah[mt][2] = Ah[kk + t + 4][rb + g];
                ah[mt][3] = Ah[kk + t + 4][rb + g + 8];
                al[mt][0] = Al[kk + t][rb + g];
                al[mt][1] = Al[kk + t][rb + g + 8];
                al[mt][2] = Al[kk + t + 4][rb + g];
                al[mt][3] = Al[kk + t + 4][rb + g + 8];
            }
            #pragma unroll
            for (int nt = 0; nt < 4; nt++) {
                int nb = wx * 32 + nt * 8;
                uint32_t bh0 = Bh[kk + t][nb + g];
                uint32_t bh1 = Bh[kk + t + 4][nb + g];
                uint32_t bl0 = Bl[kk + t][nb + g];
                uint32_t bl1 = Bl[kk + t + 4][nb + g];
                #pragma unroll
                for (int mt = 0; mt < 2; mt++) {
                    mma8(acc[mt][nt], ah[mt][0], ah[mt][1], ah[mt][2], ah[mt][3], bh0, bh1);
                    mma8(acc[mt][nt], ah[mt][0], ah[mt][1], ah[mt][2], ah[mt][3], bl0, bl1);
                    mma8(acc[mt][nt], al[mt][0], al[mt][1], al[mt][2], al[mt][3], bh0, bh1);
                }
            }
        }
    }

    // Epilogue: +bias, scatter to [B,H,S,hd]
    const int h = n0 >> 6;
    #pragma unroll
    for (int mt = 0; mt < 2; mt++) {
        #pragma unroll
        for (int hs = 0; hs < 2; hs++) {
            int mg = m0 + wy * 32 + mt * 16 + g + hs * 8;
            int bb = mg >> 11;
            int s  = mg & (SEQ - 1);
            float* orow = out + ((bb * NHEAD + h) * SEQ + s) * HDIM;
            #pragma unroll
            for (int nt = 0; nt < 4; nt++) {
                int d = wx * 32 + nt * 8 + 2 * t;
                float2 v;
                v.x = acc[mt][nt][hs * 2 + 0] + bias[n0 + d];
                v.y = acc[mt][nt][hs * 2 + 1] + bias[n0 + d + 1];
                *reinterpret_cast<float2*>(orow + d) = v;
            }
        }
    }
}

// ---------------------------------------------------------------------------
// Kernel 2: flash attention, tf32 tensor cores, persistent + dynamic queue.
// 256 thr (8 warps), BM=128 q rows, key tile 64. Warp w owns q rows
// [16w,16w+16): softmax warp-local (width-4 shfl). Score scale folded into Q.
// ---------------------------------------------------------------------------
__global__ __launch_bounds__(256, 2) void attn_kernel(
    const float* __restrict__ mask, float* __restrict__ out)
{
    extern __shared__ uint32_t sm4[];
    uint32_t* Qs = sm4;                 // [128][68] tf32 (pre-scaled by 1/8)
    uint32_t* Ks = Qs + 128 * 68;       // [64][68]
    uint32_t* Vs = Ks + 64 * 68;        // [64][72]
    uint32_t* Ps = Vs + 64 * 72;        // [128][68] tf32 probs
    float*    Ms = (float*)(Ps + 128 * 68);  // [64] mask tile

    const int tid  = threadIdx.x;
    const int warp = tid >> 5;
    const int lane = tid & 31;
    const int g = lane >> 2;
    const int t = lane & 3;
    const int wbase = warp * 16;

    int tile = blockIdx.x;
    while (tile < NTILES) {
        const int pair = tile >> 4;          // / QTILES
        const int qt   = tile & (QTILES - 1);
        const int bb = pair / NHEAD;
        const int hh = pair % NHEAD;
        const int q0 = qt * 128;

        const float* __restrict__ Qg = g_q + (bb * NHEAD + hh) * SEQ * HDIM;
        const float* __restrict__ Kg = g_k + (bb * NHEAD + hh) * SEQ * HDIM;
        const float* __restrict__ Vg = g_v + (bb * NHEAD + hh) * SEQ * HDIM;

        __syncthreads();   // prior tile done with all smem
        // Load Q tile (128x64), scale by 1/8 (exact), convert to tf32
        {
            const float4* Q4 = reinterpret_cast<const float4*>(Qg + q0 * HDIM);
            #pragma unroll
            for (int e = 0; e < 8; e++) {
                int idx = tid + e * 256;
                int r = idx >> 4, c4 = idx & 15;
                float4 v = Q4[idx];
                uint32_t* dst = Qs + r * 68 + c4 * 4;
                dst[0] = f2tf(v.x * 0.125f); dst[1] = f2tf(v.y * 0.125f);
                dst[2] = f2tf(v.z * 0.125f); dst[3] = f2tf(v.w * 0.125f);
            }
        }

        float o[8][4] = {};
        float m_run[2] = {-1e30f, -1e30f}, l_run[2] = {0.f, 0.f};

        for (int k0 = 0; k0 < SEQ; k0 += 64) {
            __syncthreads();   // prev iter done with Ks/Vs (+ Q load iter 0)
            {
                const float4* K4 = reinterpret_cast<const float4*>(Kg + k0 * HDIM);
                const float4* V4 = reinterpret_cast<const float4*>(Vg + k0 * HDIM);
                #pragma unroll
                for (int e = 0; e < 4; e++) {
                    int idx = tid + e * 256;
                    int r = idx >> 4, c4 = idx & 15;
                    float4 kv = K4[idx];
                    uint32_t* dk = Ks + r * 68 + c4 * 4;
                    dk[0] = f2tf(kv.x); dk[1] = f2tf(kv.y);
                    dk[2] = f2tf(kv.z); dk[3] = f2tf(kv.w);
                    float4 vv = V4[idx];
                    uint32_t* dv = Vs + r * 72 + c4 * 4;
                    dv[0] = f2tf(vv.x); dv[1] = f2tf(vv.y);
                    dv[2] = f2tf(vv.z); dv[3] = f2tf(vv.w);
                }
                if (tid < 64) Ms[tid] = mask[bb * SEQ + k0 + tid];
            }
            __syncthreads();

            // ---- S = Q K^T : warp m16 x n64, k=64 ----
            float s[8][4] = {};
            #pragma unroll
            for (int kk = 0; kk < 8; kk++) {
                const uint32_t* q0p = Qs + (wbase + g) * 68 + kk * 8;
                const uint32_t* q1p = Qs + (wbase + g + 8) * 68 + kk * 8;
                uint32_t a0 = q0p[t],     a1 = q1p[t];
                uint32_t a2 = q0p[t + 4], a3 = q1p[t + 4];
                #pragma unroll
                for (int nt = 0; nt < 8; nt++) {
                    uint32_t b0 = Ks[(nt * 8 + g) * 68 + kk * 8 + t];
                    uint32_t b1 = Ks[(nt * 8 + g) * 68 + kk * 8 + t + 4];
                    mma8(s[nt], a0, a1, a2, a3, b0, b1);
                }
            }

            // ---- online softmax (rows wbase+g, wbase+g+8) ----
            float2 mk2[8];
            #pragma unroll
            for (int nt = 0; nt < 8; nt++)
                mk2[nt] = *reinterpret_cast<const float2*>(Ms + nt * 8 + 2 * t);

            #pragma unroll
            for (int hs = 0; hs < 2; hs++) {
                float mm = -1e30f;
                #pragma unroll
                for (int nt = 0; nt < 8; nt++) {
                    float v0 = s[nt][hs * 2 + 0] + mk2[nt].x;
                    float v1 = s[nt][hs * 2 + 1] + mk2[nt].y;
                    s[nt][hs * 2 + 0] = v0;
                    s[nt][hs * 2 + 1] = v1;
                    mm = fmaxf(mm, fmaxf(v0, v1));
                }
                mm = fmaxf(mm, __shfl_xor_sync(0xffffffffu, mm, 1));
                mm = fmaxf(mm, __shfl_xor_sync(0xffffffffu, mm, 2));

                float mn = fmaxf(m_run[hs], mm);
                float alpha = __expf(m_run[hs] - mn);
                m_run[hs] = mn;

                float ps = 0.f;
                #pragma unroll
                for (int nt = 0; nt < 8; nt++) {
                    float p0 = __expf(s[nt][hs * 2 + 0] - mn);
                    float p1 = __expf(s[nt][hs * 2 + 1] - mn);
                    s[nt][hs * 2 + 0] = p0;
                    s[nt][hs * 2 + 1] = p1;
                    ps += p0 + p1;
                }
                ps += __shfl_xor_sync(0xffffffffu, ps, 1);
                ps += __shfl_xor_sync(0xffffffffu, ps, 2);
                l_run[hs] = l_run[hs] * alpha + ps;

                #pragma unroll
                for (int nt = 0; nt < 8; nt++) {
                    o[nt][hs * 2 + 0] *= alpha;
                    o[nt][hs * 2 + 1] *= alpha;
                }
            }

            // ---- stage P (tf32) into Ps: own warp's 16 rows ----
            #pragma unroll
            for (int nt = 0; nt < 8; nt++) {
                uint2 p0, p1;
                p0.x = f2tf(s[nt][0]); p0.y = f2tf(s[nt][1]);
                p1.x = f2tf(s[nt][2]); p1.y = f2tf(s[nt][3]);
                *reinterpret_cast<uint2*>(Ps + (wbase + g) * 68 + nt * 8 + 2 * t) = p0;
                *reinterpret_cast<uint2*>(Ps + (wbase + g + 8) * 68 + nt * 8 + 2 * t) = p1;
            }
            __syncwarp();

            // ---- O += P V : warp m16 x n64, k=64 (keys) ----
            #pragma unroll
            for (int kk = 0; kk < 8; kk++) {
                const uint32_t* p0p = Ps + (wbase + g) * 68 + kk * 8;
                const uint32_t* p1p = Ps + (wbase + g + 8) * 68 + kk * 8;
                uint32_t a0 = p0p[t],     a1 = p1p[t];
                uint32_t a2 = p0p[t + 4], a3 = p1p[t + 4];
                #pragma unroll
                for (int nt = 0; nt < 8; nt++) {
                    uint32_t b0 = Vs[(kk * 8 + t) * 72 + nt * 8 + g];
                    uint32_t b1 = Vs[(kk * 8 + t + 4) * 72 + nt * 8 + g];
                    mma8(o[nt], a0, a1, a2, a3, b0, b1);
                }
            }
        }

        // ---- normalize + write out [B,S,D] ----
        #pragma unroll
        for (int hs = 0; hs < 2; hs++) {
            int r = q0 + wbase + g + hs * 8;
            float inv = 1.f / l_run[hs];
            float* orow = out + (bb * SEQ + r) * DMODEL + hh * HDIM;
            #pragma unroll
            for (int nt = 0; nt < 8; nt++) {
                float2 v;
                v.x = o[nt][hs * 2 + 0] * inv;
                v.y = o[nt][hs * 2 + 1] * inv;
                *reinterpret_cast<float2*>(orow + nt * 8 + 2 * t) = v;
            }
        }

        // grab next tile from the dynamic queue
        if (tid == 0)
            *((unsigned int*)Ms) = atomicAdd(&g_ctr, 1u);  // reuse Ms slot
        __syncthreads();
        tile = *((unsigned int*)Ms);
    }
}

// ---------------------------------------------------------------------------
extern "C" void kernel_launch(void* const* d_in, const int* in_sizes, int n_in,
                              void* d_out, int out_size)
{
    const float* v1   = (const float*)d_in[0];
    const float* mask = (const float*)d_in[1];
    const float* Wq   = (const float*)d_in[2];
    const float* bq   = (const float*)d_in[3];
    const float* Wk   = (const float*)d_in[4];
    const float* bk   = (const float*)d_in[5];
    const float* Wv   = (const float*)d_in[6];
    const float* bv   = (const float*)d_in[7];
    float* out = (float*)d_out;

    // QKV: grid (12 n-tiles, 32 m-tiles, 3 matrices), 256 threads
    dim3 g1(DMODEL / 64, MROWS / 128, 3);
    qkv_kernel<<<g1, 256>>>(v1, Wq, bq, Wk, bk, Wv, bv);

    // Attention: persistent grid, dynamic tile queue, 105.7 KB smem
    const int smem_bytes = (128 * 68 + 64 * 68 + 64 * 72 + 128 * 68 + 64) * 4;
    cudaFuncSetAttribute(attn_kernel, cudaFuncAttributeMaxDynamicSharedMemorySize,
                         smem_bytes);
    attn_kernel<<<ATTN_GRID, 256, smem_bytes>>>(mask, out);
}